// round 5
// baseline (speedup 1.0000x reference)
#include <cuda_runtime.h>

#define NS 16
#define NZ 1000
#define NX 1000

#define DT_F    0.001f
#define HDT_F   0.0005f   // dt/2
#define INV_H_F 0.1f      // 1/h

#define AXW    (NX - 1)   // 999
#define AZW    (NX - 2)   // 998
#define AXROWS (NZ - 2)   // 998
#define AZROWS (NZ - 1)   // 999

#define TW 128            // tile width (x)
#define TH 8              // tile height (z); block (128,2), 4 rows/thread

// Scalar P at one point (x-halo only)
__device__ __forceinline__ float compute_p_point(
    const float* __restrict__ Px, const float* __restrict__ Pz,
    const float* __restrict__ Ax, const float* __restrict__ Az,
    const float* __restrict__ src, const float* __restrict__ m2dt,
    const float* __restrict__ sigx, const float* __restrict__ sigz,
    int sOffP, int sOffAx, int sOffAz, int z, int x)
{
    float ax_x = 0.f, az_z = 0.f;
    if (z >= 1 && z <= NZ - 2 && x >= 1 && x <= NX - 2) {
        const float* axr = Ax + sOffAx + (z - 1) * AXW;
        ax_x = (__ldcs(axr + x) - __ldcs(axr + x - 1)) * INV_H_F;
        const float* azp = Az + sOffAz + (x - 1);
        az_z = (__ldcs(azp + z * AZW) - __ldcs(azp + (z - 1) * AZW)) * INV_H_F;
    }
    const int g2 = z * NX + x;
    const int g3 = sOffP + g2;
    const float sx = sigx[g2] * HDT_F;
    const float sz = sigz[g2] * HDT_F;
    const float m  = m2dt[g2];
    const float pxn = __fdividef(fmaf(m, ax_x, (1.f - sx) * __ldcs(Px + g3)), 1.f + sx);
    const float pzn = __fdividef(fmaf(m, az_z, (1.f - sz) * __ldcs(Pz + g3)), 1.f + sz);
    return pxn + pzn + __ldcs(src + g3) * DT_F;
}

__global__ __launch_bounds__(256)
void pml_step_kernel(
    const float* __restrict__ Px,   const float* __restrict__ Pz,
    const float* __restrict__ Ax,   const float* __restrict__ Az,
    const float* __restrict__ src,
    const float* __restrict__ m2dt,
    const float* __restrict__ sigx, const float* __restrict__ sxh,
    const float* __restrict__ sigz, const float* __restrict__ szh,
    float* __restrict__ oPx, float* __restrict__ oPz,
    float* __restrict__ oAx, float* __restrict__ oAz,
    float* __restrict__ oP)
{
    __shared__ float sP[TH + 1][TW + 4];   // rows z0..z0+8, cols x0..x0+128 (col 128 = x-halo)

    const int s  = blockIdx.z;
    const int z0 = blockIdx.y * TH;
    const int x0 = blockIdx.x * TW;
    const int tx = threadIdx.x;            // 0..127 -> x
    const int ty = threadIdx.y;            // 0..1   -> z quartet
    const int x  = x0 + tx;
    const int zb = z0 + 4 * ty;
    const int tid = ty * TW + tx;

    const int sOffP  = s * (NZ * NX);
    const int sOffAx = s * (AXROWS * AXW);
    const int sOffAz = s * (AZROWS * AZW);

    float pReg[4], axReg[4] = {0.f, 0.f, 0.f, 0.f}, azReg[4] = {0.f, 0.f, 0.f, 0.f};

    const bool xact = (x < NX);
    const bool xin  = (x >= 1) && (x <= NX - 2);

    float azprev = 0.f;
    if (xact && xin && zb >= 1)
        azprev = __ldcs(Az + sOffAz + (zb - 1) * AZW + (x - 1));

    // ---- Phase 1: 4 rows per thread, all loads coalesced ----
    if (xact) {
        #pragma unroll
        for (int r = 0; r < 4; r++) {
            const int z  = zb + r;
            const int g2 = z * NX + x;
            const int g3 = sOffP + g2;
            const bool zin = (z >= 1) && (z <= NZ - 2);

            float axc = 0.f, axm = 0.f, azc = 0.f;
            if (zin) {
                const float* axr = Ax + sOffAx + (z - 1) * AXW;
                if (x <= NX - 2) axc = __ldcs(axr + x);
                if (x >= 1)      axm = __ldcs(axr + x - 1);
            }
            if (z <= NZ - 2 && xin)
                azc = __ldcs(Az + sOffAz + z * AZW + (x - 1));

            float ax_x = 0.f, az_z = 0.f;
            if (zin && xin) {
                ax_x = (axc - axm) * INV_H_F;
                az_z = (azc - azprev) * INV_H_F;
            }

            const float pxv = __ldcs(Px + g3);
            const float pzv = __ldcs(Pz + g3);
            const float srv = __ldcs(src + g3);
            const float m   = m2dt[g2];
            const float sx  = sigx[g2] * HDT_F;
            const float sz  = sigz[g2] * HDT_F;

            const float pxn = __fdividef(fmaf(m, ax_x, (1.f - sx) * pxv), 1.f + sx);
            const float pzn = __fdividef(fmaf(m, az_z, (1.f - sz) * pzv), 1.f + sz);
            const float p   = pxn + pzn + srv * DT_F;

            __stcs(oPx + g3, pxn);
            __stcs(oPz + g3, pzn);
            __stcs(oP  + g3, p);
            sP[4 * ty + r][tx] = p;

            pReg[r]  = p;
            axReg[r] = axc;   // = Ax[z-1][x]   (phase 2a operand at i=z-1)
            azReg[r] = azc;   // = Az[z][x-1]   (phase 2b operand at i=z)
            azprev = azc;
        }

        // z-halo row (z0+8), computed by ty==1 (azprev = Az[z0+7][x-1] carried)
        if (ty == 1 && z0 + TH < NZ) {
            const int z  = z0 + TH;
            const int g2 = z * NX + x;
            const int g3 = sOffP + g2;
            const bool zin = (z <= NZ - 2);   // z >= 1 always here

            float axc = 0.f, axm = 0.f, azc = 0.f;
            if (zin) {
                const float* axr = Ax + sOffAx + (z - 1) * AXW;
                if (x <= NX - 2) axc = __ldcs(axr + x);
                if (x >= 1)      axm = __ldcs(axr + x - 1);
                if (xin)         azc = __ldcs(Az + sOffAz + z * AZW + (x - 1));
            }
            float ax_x = 0.f, az_z = 0.f;
            if (zin && xin) {
                ax_x = (axc - axm) * INV_H_F;
                az_z = (azc - azprev) * INV_H_F;
            }
            const float m  = m2dt[g2];
            const float sx = sigx[g2] * HDT_F;
            const float sz = sigz[g2] * HDT_F;
            const float pxn = __fdividef(fmaf(m, ax_x, (1.f - sx) * __ldcs(Px + g3)), 1.f + sx);
            const float pzn = __fdividef(fmaf(m, az_z, (1.f - sz) * __ldcs(Pz + g3)), 1.f + sz);
            sP[TH][tx] = pxn + pzn + __ldcs(src + g3) * DT_F;
        }
    }

    // x-halo column (x0+128), rows z0..z0+7, 8 threads
    if (tid < TH && x0 + TW < NX) {
        sP[tid][TW] = compute_p_point(Px, Pz, Ax, Az, src, m2dt, sigx, sigz,
                                      sOffP, sOffAx, sOffAz, z0 + tid, x0 + TW);
    }

    __syncthreads();

    if (!xact) return;

    // ---- Phase 2a: Ax_n at (i = z-1, j = x) ----
    if (x <= NX - 2) {
        #pragma unroll
        for (int r = 0; r < 4; r++) {
            const int i = zb + r - 1;
            if (i >= 0 && i <= NZ - 3) {
                const float d  = (sP[4 * ty + r][tx + 1] - pReg[r]) * INV_H_F;
                const float sv = sxh[i * AXW + x] * HDT_F;
                __stcs(oAx + sOffAx + i * AXW + x,
                       __fdividef(fmaf(DT_F, d, (1.f - sv) * axReg[r]), 1.f + sv));
            }
        }
    }

    // ---- Phase 2b: Az_n at (i = z, j = x-1) ----
    if (xin) {
        #pragma unroll
        for (int r = 0; r < 4; r++) {
            const int i = zb + r;
            if (i <= NZ - 2) {
                const float pnext = (r < 3) ? pReg[r + 1] : sP[4 * ty + 4][tx];
                const float d  = (pnext - pReg[r]) * INV_H_F;
                const float sv = szh[i * AZW + (x - 1)] * HDT_F;
                __stcs(oAz + sOffAz + i * AZW + (x - 1),
                       __fdividef(fmaf(DT_F, d, (1.f - sv) * azReg[r]), 1.f + sv));
            }
        }
    }
}

extern "C" void kernel_launch(void* const* d_in, const int* in_sizes, int n_in,
                              void* d_out, int out_size)
{
    const float* Px   = (const float*)d_in[0];
    const float* Pz   = (const float*)d_in[1];
    const float* Ax   = (const float*)d_in[2];
    const float* Az   = (const float*)d_in[3];
    const float* src  = (const float*)d_in[4];
    const float* m2dt = (const float*)d_in[5];
    const float* sigx = (const float*)d_in[6];
    const float* sxh  = (const float*)d_in[7];
    const float* sigz = (const float*)d_in[8];
    const float* szh  = (const float*)d_in[9];

    float* out = (float*)d_out;
    const long long NP  = (long long)NS * NZ * NX;
    const long long NAX = (long long)NS * AXROWS * AXW;
    const long long NAZ = (long long)NS * AZROWS * AZW;

    float* oPx = out;
    float* oPz = oPx + NP;
    float* oAx = oPz + NP;
    float* oAz = oAx + NAX;
    float* oP  = oAz + NAZ;

    dim3 block(TW, 2, 1);
    dim3 grid((NX + TW - 1) / TW, (NZ + TH - 1) / TH, NS);

    pml_step_kernel<<<grid, block>>>(Px, Pz, Ax, Az, src,
                                     m2dt, sigx, sxh, sigz, szh,
                                     oPx, oPz, oAx, oAz, oP);
}

// round 11
// speedup vs baseline: 1.1645x; 1.1645x over previous
#include <cuda_runtime.h>

#define NS 16
#define NZ 1000
#define NX 1000

#define DT_F    0.001f
#define HDT_F   0.0005f
#define INV_H_F 0.1f

#define AXW    999
#define AZW    998
#define AXROWS 998
#define AZROWS 999
#define TOT_AX (NS * AXROWS * AXW)
#define TOT_AZ (NS * AZROWS * AZW)

#define TZ 8
#define TILEW 128

template<bool STREAM>
__device__ __forceinline__ float4 ldg4_guard(const float* __restrict__ g, int f0, int tot)
{
    if (f0 >= 0 && f0 + 3 < tot)
        return STREAM ? __ldcs((const float4*)(g + f0)) : *(const float4*)(g + f0);
    float t[4];
    #pragma unroll
    for (int k = 0; k < 4; k++) {
        const int fi = f0 + k;
        t[k] = (fi >= 0 && fi < tot) ? (STREAM ? __ldcs(g + fi) : g[fi]) : 0.f;
    }
    return make_float4(t[0], t[1], t[2], t[3]);
}

// Warp-cooperative aligned window load. w[0..7] = flat elements
// [A0+4*lane .. A0+4*lane+7], A0 = F - (F&3). Returns d = F&3 (warp-uniform).
// Lane's 5-value window starting at flat F+4*lane is w[d..d+4].
template<bool STREAM>
__device__ __forceinline__ int warp_window(const float* __restrict__ g, int F, int tot,
                                           int lane, float w[8])
{
    const int d  = F & 3;
    const int A0 = F - d;
    float4 v = ldg4_guard<STREAM>(g, A0 + 4 * lane, tot);
    float4 vn;
    vn.x = __shfl_down_sync(0xffffffffu, v.x, 1);
    vn.y = __shfl_down_sync(0xffffffffu, v.y, 1);
    vn.z = __shfl_down_sync(0xffffffffu, v.z, 1);
    vn.w = __shfl_down_sync(0xffffffffu, v.w, 1);
    if (lane == 31) vn = ldg4_guard<STREAM>(g, A0 + 128, tot);
    w[0] = v.x;  w[1] = v.y;  w[2] = v.z;  w[3] = v.w;
    w[4] = vn.x; w[5] = vn.y; w[6] = vn.z; w[7] = vn.w;
    return d;
}

__device__ __forceinline__ void extract5(const float w[8], int d, float o[5])
{
    switch (d) {
        case 0:  o[0]=w[0]; o[1]=w[1]; o[2]=w[2]; o[3]=w[3]; o[4]=w[4]; break;
        case 1:  o[0]=w[1]; o[1]=w[2]; o[2]=w[3]; o[3]=w[4]; o[4]=w[5]; break;
        case 2:  o[0]=w[2]; o[1]=w[3]; o[2]=w[4]; o[3]=w[5]; o[4]=w[6]; break;
        default: o[0]=w[3]; o[1]=w[4]; o[2]=w[5]; o[3]=w[6]; o[4]=w[7]; break;
    }
}
__device__ __forceinline__ void extract4(const float w[8], int d, float o[4])
{
    switch (d) {
        case 0:  o[0]=w[0]; o[1]=w[1]; o[2]=w[2]; o[3]=w[3]; break;
        case 1:  o[0]=w[1]; o[1]=w[2]; o[2]=w[3]; o[3]=w[4]; break;
        case 2:  o[0]=w[2]; o[1]=w[3]; o[2]=w[4]; o[3]=w[5]; break;
        default: o[0]=w[3]; o[1]=w[4]; o[2]=w[5]; o[3]=w[6]; break;
    }
}

// Warp-cooperative aligned row store with EXACT coverage.
// Lane's vals[c] targets flat F+4*lane+c, column jcol0+4*lane+c in [0..jmax].
// Own vector (if it fires) covers vals[c] for c < 4-d; lane+1's vector covers
// c >= 4-d. Ballot tells each lane whether its successor's vector fired; any
// uncovered value is stored scalar (bounds-masked). Must be called with all
// 32 lanes active (warp-uniform guard).
__device__ __forceinline__ void warp_store_row(
    float* __restrict__ g, int F, int jcol0, int jmax, const float vals[4], int lane)
{
    const int d = F & 3;
    const float up0 = __shfl_up_sync(0xffffffffu, vals[0], 1);
    const float up1 = __shfl_up_sync(0xffffffffu, vals[1], 1);
    const float up2 = __shfl_up_sync(0xffffffffu, vals[2], 1);
    const float up3 = __shfl_up_sync(0xffffffffu, vals[3], 1);
    float4 sv;
    switch (d) {
        case 0:  sv = make_float4(vals[0], vals[1], vals[2], vals[3]); break;
        case 1:  sv = make_float4(up3, vals[0], vals[1], vals[2]); break;
        case 2:  sv = make_float4(up2, up3, vals[0], vals[1]); break;
        default: sv = make_float4(up1, up2, up3, vals[0]); break;
    }
    const int j0 = jcol0 + 4 * lane - d;          // column of sv.x
    const bool vecok = (d == 0 || lane >= 1) && (j0 >= 0) && (j0 + 3 <= jmax);
    const unsigned bal = __ballot_sync(0xffffffffu, vecok);
    if (vecok) __stcs((float4*)(g + (F - d) + 4 * lane), sv);

    const bool next_ok = (lane < 31) && ((bal >> (lane + 1)) & 1u);
    #pragma unroll
    for (int c = 0; c < 4; c++) {
        const bool covered = (d == 0) ? vecok : ((c < 4 - d) ? vecok : next_ok);
        if (!covered) {
            const int j = jcol0 + 4 * lane + c;
            if (j >= 0 && j <= jmax) __stcs(g + F + 4 * lane + c, vals[c]);
        }
    }
}

// Scalar P at one point (halo only)
__device__ __forceinline__ float compute_p_point(
    const float* __restrict__ Px, const float* __restrict__ Pz,
    const float* __restrict__ Ax, const float* __restrict__ Az,
    const float* __restrict__ src, const float* __restrict__ m2dt,
    const float* __restrict__ sigx, const float* __restrict__ sigz,
    int sOffP, int sOffAx, int sOffAz, int z, int x)
{
    float ax_x = 0.f, az_z = 0.f;
    if (z >= 1 && z <= NZ - 2 && x >= 1 && x <= NX - 2) {
        const float* axr = Ax + sOffAx + (z - 1) * AXW;
        ax_x = (__ldcs(axr + x) - __ldcs(axr + x - 1)) * INV_H_F;
        const float* azp = Az + sOffAz + (x - 1);
        az_z = (__ldcs(azp + z * AZW) - __ldcs(azp + (z - 1) * AZW)) * INV_H_F;
    }
    const int g2 = z * NX + x;
    const int g3 = sOffP + g2;
    const float sx = sigx[g2] * HDT_F;
    const float sz = sigz[g2] * HDT_F;
    const float m  = m2dt[g2];
    const float pxn = __fdividef(fmaf(m, ax_x, (1.f - sx) * __ldcs(Px + g3)), 1.f + sx);
    const float pzn = __fdividef(fmaf(m, az_z, (1.f - sz) * __ldcs(Pz + g3)), 1.f + sz);
    return pxn + pzn + __ldcs(src + g3) * DT_F;
}

__global__ __launch_bounds__(256, 4)
void pml_step_kernel(
    const float* __restrict__ Px,   const float* __restrict__ Pz,
    const float* __restrict__ Ax,   const float* __restrict__ Az,
    const float* __restrict__ src,
    const float* __restrict__ m2dt,
    const float* __restrict__ sigx, const float* __restrict__ sxh,
    const float* __restrict__ sigz, const float* __restrict__ szh,
    float* __restrict__ oPx, float* __restrict__ oPz,
    float* __restrict__ oAx, float* __restrict__ oAz,
    float* __restrict__ oP)
{
    __shared__ float sP[TZ + 1][TILEW + 4];   // rows z0..z0+8, col 128 = x-halo

    const int s  = blockIdx.z;
    const int z0 = blockIdx.y * TZ;
    const int x0 = blockIdx.x * TILEW;
    const int tx = threadIdx.x;     // lane
    const int ty = threadIdx.y;     // z row
    const int tid = ty * 32 + tx;
    const int x  = x0 + 4 * tx;
    const int z  = z0 + ty;

    const int sOffP  = s * (NZ * NX);
    const int sOffAx = s * (AXROWS * AXW);
    const int sOffAz = s * (AZROWS * AZW);

    const bool xact = (x < NX);
    const bool zin  = (z >= 1) && (z <= NZ - 2);

    // ---- Phase 1 loads ----
    float4 pxv = make_float4(0,0,0,0), pzv = pxv, srv = pxv, mv = pxv, sxv = pxv, szv = pxv;
    const int g2 = z * NX + x;
    const int g3 = sOffP + g2;
    if (xact) {
        pxv = __ldcs((const float4*)(Px + g3));
        pzv = __ldcs((const float4*)(Pz + g3));
        srv = __ldcs((const float4*)(src + g3));
        mv  = *(const float4*)(m2dt + g2);
        sxv = *(const float4*)(sigx + g2);
        szv = *(const float4*)(sigz + g2);
    }

    float wbuf[8];
    float axv[5], azlo[4], azhi[4];
    {
        const int dAx = warp_window<true>(Ax, sOffAx + (z - 1) * AXW + x0 - 1, TOT_AX, tx, wbuf);
        extract5(wbuf, dAx, axv);                 // Ax[z-1][x-1 .. x+3]
    }
    {
        const int dA0 = warp_window<true>(Az, sOffAz + (z - 1) * AZW + x0 - 1, TOT_AZ, tx, wbuf);
        extract4(wbuf, dA0, azlo);                // Az[z-1][x-1 .. x+2]
    }
    {
        const int dA1 = warp_window<true>(Az, sOffAz + z * AZW + x0 - 1, TOT_AZ, tx, wbuf);
        extract4(wbuf, dA1, azhi);                // Az[z][x-1 .. x+2]
    }

    // ---- Phase 1 compute + stores ----
    float pReg[4];
    if (xact) {
        const float px_in[4] = {pxv.x, pxv.y, pxv.z, pxv.w};
        const float pz_in[4] = {pzv.x, pzv.y, pzv.z, pzv.w};
        const float sr_in[4] = {srv.x, srv.y, srv.z, srv.w};
        const float m_in[4]  = {mv.x, mv.y, mv.z, mv.w};
        const float sx_in[4] = {sxv.x, sxv.y, sxv.z, sxv.w};
        const float sz_in[4] = {szv.x, szv.y, szv.z, szv.w};

        float pxn[4], pzn[4];
        #pragma unroll
        for (int c = 0; c < 4; c++) {
            const int xi = x + c;
            const bool m = zin && (xi >= 1) && (xi <= NX - 2);
            const float ax_x = m ? (axv[c + 1] - axv[c]) * INV_H_F : 0.f;
            const float az_z = m ? (azhi[c] - azlo[c]) * INV_H_F : 0.f;
            const float sx = sx_in[c] * HDT_F;
            const float sz = sz_in[c] * HDT_F;
            pxn[c] = __fdividef(fmaf(m_in[c], ax_x, (1.f - sx) * px_in[c]), 1.f + sx);
            pzn[c] = __fdividef(fmaf(m_in[c], az_z, (1.f - sz) * pz_in[c]), 1.f + sz);
            pReg[c] = pxn[c] + pzn[c] + sr_in[c] * DT_F;
        }
        __stcs((float4*)(oPx + g3), make_float4(pxn[0], pxn[1], pxn[2], pxn[3]));
        __stcs((float4*)(oPz + g3), make_float4(pzn[0], pzn[1], pzn[2], pzn[3]));
        __stcs((float4*)(oP  + g3), make_float4(pReg[0], pReg[1], pReg[2], pReg[3]));
        *(float4*)&sP[ty][4 * tx] = make_float4(pReg[0], pReg[1], pReg[2], pReg[3]);
    } else {
        pReg[0] = pReg[1] = pReg[2] = pReg[3] = 0.f;
    }

    // ---- Halo P ----
    if (tid < TILEW) {
        const int hz = z0 + TZ;
        const int hx = x0 + tid;
        if (hz < NZ && hx < NX)
            sP[TZ][tid] = compute_p_point(Px, Pz, Ax, Az, src, m2dt, sigx, sigz,
                                          sOffP, sOffAx, sOffAz, hz, hx);
    } else if (tid < TILEW + TZ) {
        const int r  = tid - TILEW;
        const int hx = x0 + TILEW;
        if (hx < NX)
            sP[r][TILEW] = compute_p_point(Px, Pz, Ax, Az, src, m2dt, sigx, sigz,
                                           sOffP, sOffAx, sOffAz, z0 + r, hx);
    }

    __syncthreads();

    // ---- Phase 2a: Ax_n row i = z-1 (warp-uniform guard) ----
    if (zin) {
        float wSx[8];
        const int dSx = warp_window<false>(sxh, (z - 1) * AXW + x0, AXROWS * AXW, tx, wSx);
        float sxw[4];
        extract4(wSx, dSx, sxw);                  // sxh[z-1][x .. x+3]

        float pe = __shfl_down_sync(0xffffffffu, pReg[0], 1);   // P[z][x+4]
        if (tx == 31) pe = sP[ty][TILEW];

        float vals[4];
        #pragma unroll
        for (int c = 0; c < 4; c++) {
            const float pnext = (c < 3) ? pReg[c + 1] : pe;
            const float dfx = (pnext - pReg[c]) * INV_H_F;
            const float sv  = sxw[c] * HDT_F;
            vals[c] = __fdividef(fmaf(DT_F, dfx, (1.f - sv) * axv[c + 1]), 1.f + sv);
        }
        warp_store_row(oAx, sOffAx + (z - 1) * AXW + x0, x0, AXW - 1, vals, tx);
    }

    // ---- Phase 2b: Az_n row i = z (warp-uniform guard) ----
    if (z <= NZ - 2) {
        float wSz[8];
        const int dSz = warp_window<false>(szh, z * AZW + x0 - 1, AZROWS * AZW, tx, wSz);
        float szw[4];
        extract4(wSz, dSz, szw);                  // szh[z][x-1 .. x+2]

        const float4 pb = *(const float4*)&sP[ty + 1][4 * tx];
        const float pbv[4] = {pb.x, pb.y, pb.z, pb.w};

        float vals[4];
        #pragma unroll
        for (int c = 0; c < 4; c++) {
            const float dfz = (pbv[c] - pReg[c]) * INV_H_F;
            const float sv  = szw[c] * HDT_F;
            vals[c] = __fdividef(fmaf(DT_F, dfz, (1.f - sv) * azhi[c]), 1.f + sv);
        }
        warp_store_row(oAz, sOffAz + z * AZW + x0 - 1, x0 - 1, AZW - 1, vals, tx);
    }
}

extern "C" void kernel_launch(void* const* d_in, const int* in_sizes, int n_in,
                              void* d_out, int out_size)
{
    const float* Px   = (const float*)d_in[0];
    const float* Pz   = (const float*)d_in[1];
    const float* Ax   = (const float*)d_in[2];
    const float* Az   = (const float*)d_in[3];
    const float* src  = (const float*)d_in[4];
    const float* m2dt = (const float*)d_in[5];
    const float* sigx = (const float*)d_in[6];
    const float* sxh  = (const float*)d_in[7];
    const float* sigz = (const float*)d_in[8];
    const float* szh  = (const float*)d_in[9];

    float* out = (float*)d_out;
    const long long NP  = (long long)NS * NZ * NX;
    const long long NAX = (long long)NS * AXROWS * AXW;
    const long long NAZ = (long long)NS * AZROWS * AZW;

    float* oPx = out;
    float* oPz = oPx + NP;
    float* oAx = oPz + NP;
    float* oAz = oAx + NAX;
    float* oP  = oAz + NAZ;

    dim3 block(32, TZ, 1);
    dim3 grid((NX + TILEW - 1) / TILEW, NZ / TZ, NS);

    pml_step_kernel<<<grid, block>>>(Px, Pz, Ax, Az, src,
                                     m2dt, sigx, sxh, sigz, szh,
                                     oPx, oPz, oAx, oAz, oP);
}

// round 12
// speedup vs baseline: 1.3881x; 1.1921x over previous
#include <cuda_runtime.h>

#define NS 16
#define NZ 1000
#define NX 1000

#define DT_F    0.001f
#define HDT_F   0.0005f
#define INV_H_F 0.1f

#define AXW    999
#define AZW    998
#define AXROWS 998
#define AZROWS 999
#define TOT_AX (NS * AXROWS * AXW)
#define TOT_AZ (NS * AZROWS * AZW)

#define TZ 8
#define TILEW 128

__device__ __forceinline__ float4 ldg4_guard(const float* __restrict__ g, int f0, int tot)
{
    if (f0 >= 0 && f0 + 3 < tot)
        return *(const float4*)(g + f0);
    float t[4];
    #pragma unroll
    for (int k = 0; k < 4; k++) {
        const int fi = f0 + k;
        t[k] = (fi >= 0 && fi < tot) ? g[fi] : 0.f;
    }
    return make_float4(t[0], t[1], t[2], t[3]);
}

// Warp-cooperative aligned window load (coeff arrays). w[0..7] = flat elements
// [A0+4*lane .. A0+4*lane+7], A0 = F-(F&3). Returns d = F&3. All lanes must run.
__device__ __forceinline__ int warp_window(const float* __restrict__ g, int F, int tot,
                                           int lane, float w[8])
{
    const int d  = F & 3;
    const int A0 = F - d;
    float4 v = ldg4_guard(g, A0 + 4 * lane, tot);
    float4 vn;
    vn.x = __shfl_down_sync(0xffffffffu, v.x, 1);
    vn.y = __shfl_down_sync(0xffffffffu, v.y, 1);
    vn.z = __shfl_down_sync(0xffffffffu, v.z, 1);
    vn.w = __shfl_down_sync(0xffffffffu, v.w, 1);
    if (lane == 31) vn = ldg4_guard(g, A0 + 128, tot);
    w[0] = v.x;  w[1] = v.y;  w[2] = v.z;  w[3] = v.w;
    w[4] = vn.x; w[5] = vn.y; w[6] = vn.z; w[7] = vn.w;
    return d;
}

__device__ __forceinline__ void extract4(const float w[8], int d, float o[4])
{
    switch (d) {
        case 0:  o[0]=w[0]; o[1]=w[1]; o[2]=w[2]; o[3]=w[3]; break;
        case 1:  o[0]=w[1]; o[1]=w[2]; o[2]=w[3]; o[3]=w[4]; break;
        case 2:  o[0]=w[2]; o[1]=w[3]; o[2]=w[4]; o[3]=w[5]; break;
        default: o[0]=w[3]; o[1]=w[4]; o[2]=w[5]; o[3]=w[6]; break;
    }
}

// Warp-cooperative aligned row store with exact coverage (validated R11).
// Lane's vals[c] targets flat F+4*lane+c, column jcol0+4*lane+c in [0..jmax].
__device__ __forceinline__ void warp_store_row(
    float* __restrict__ g, int F, int jcol0, int jmax, const float vals[4], int lane)
{
    const int d = F & 3;
    const float up1 = __shfl_up_sync(0xffffffffu, vals[1], 1);
    const float up2 = __shfl_up_sync(0xffffffffu, vals[2], 1);
    const float up3 = __shfl_up_sync(0xffffffffu, vals[3], 1);
    float4 sv;
    switch (d) {
        case 0:  sv = make_float4(vals[0], vals[1], vals[2], vals[3]); break;
        case 1:  sv = make_float4(up3, vals[0], vals[1], vals[2]); break;
        case 2:  sv = make_float4(up2, up3, vals[0], vals[1]); break;
        default: sv = make_float4(up1, up2, up3, vals[0]); break;
    }
    const int j0 = jcol0 + 4 * lane - d;
    const bool vecok = (d == 0 || lane >= 1) && (j0 >= 0) && (j0 + 3 <= jmax);
    const unsigned bal = __ballot_sync(0xffffffffu, vecok);
    if (vecok) __stcs((float4*)(g + (F - d) + 4 * lane), sv);

    const bool next_ok = (lane < 31) && ((bal >> (lane + 1)) & 1u);
    #pragma unroll
    for (int c = 0; c < 4; c++) {
        const bool covered = (d == 0) ? vecok : ((c < 4 - d) ? vecok : next_ok);
        if (!covered) {
            const int j = jcol0 + 4 * lane + c;
            if (j >= 0 && j <= jmax) __stcs(g + F + 4 * lane + c, vals[c]);
        }
    }
}

// Scalar P at one point (halo only)
__device__ __forceinline__ float compute_p_point(
    const float* __restrict__ Px, const float* __restrict__ Pz,
    const float* __restrict__ Ax, const float* __restrict__ Az,
    const float* __restrict__ src, const float* __restrict__ m2dt,
    const float* __restrict__ sigx, const float* __restrict__ sigz,
    int sOffP, int sOffAx, int sOffAz, int z, int x)
{
    float ax_x = 0.f, az_z = 0.f;
    if (z >= 1 && z <= NZ - 2 && x >= 1 && x <= NX - 2) {
        const float* axr = Ax + sOffAx + (z - 1) * AXW;
        ax_x = (__ldcs(axr + x) - __ldcs(axr + x - 1)) * INV_H_F;
        const float* azp = Az + sOffAz + (x - 1);
        az_z = (__ldcs(azp + z * AZW) - __ldcs(azp + (z - 1) * AZW)) * INV_H_F;
    }
    const int g2 = z * NX + x;
    const int g3 = sOffP + g2;
    const float sx = sigx[g2] * HDT_F;
    const float sz = sigz[g2] * HDT_F;
    const float m  = m2dt[g2];
    const float pxn = __fdividef(fmaf(m, ax_x, (1.f - sx) * __ldcs(Px + g3)), 1.f + sx);
    const float pzn = __fdividef(fmaf(m, az_z, (1.f - sz) * __ldcs(Pz + g3)), 1.f + sz);
    return pxn + pzn + __ldcs(src + g3) * DT_F;
}

__global__ __launch_bounds__(256, 4)
void pml_step_kernel(
    const float* __restrict__ Px,   const float* __restrict__ Pz,
    const float* __restrict__ Ax,   const float* __restrict__ Az,
    const float* __restrict__ src,
    const float* __restrict__ m2dt,
    const float* __restrict__ sigx, const float* __restrict__ sxh,
    const float* __restrict__ sigz, const float* __restrict__ szh,
    float* __restrict__ oPx, float* __restrict__ oPz,
    float* __restrict__ oAx, float* __restrict__ oAz,
    float* __restrict__ oP)
{
    __shared__ float sP[TZ + 1][TILEW + 4];

    const int s  = blockIdx.z;
    const int z0 = blockIdx.y * TZ;
    const int x0 = blockIdx.x * TILEW;
    const int tx = threadIdx.x;
    const int ty = threadIdx.y;
    const int tid = ty * 32 + tx;
    const int x  = x0 + 4 * tx;
    const int z  = z0 + ty;

    const int sOffP  = s * (NZ * NX);
    const int sOffAx = s * (AXROWS * AXW);
    const int sOffAz = s * (AZROWS * AZW);

    const bool xact = (x < NX);
    const bool zin  = (z >= 1) && (z <= NZ - 2);

    // Carry registers for phase 2
    float axk[5] = {0.f, 0.f, 0.f, 0.f, 0.f};   // axk[c+1] = Ax[z-1][x+c]
    float azk[4] = {0.f, 0.f, 0.f, 0.f};        // azk[c]   = Az[z][x-1+c]
    float sxw[4], szw[4];

    // ---- Hoisted coeff windows (latency hidden behind phase-1 compute) ----
    if (zin) {   // warp-uniform
        float wS[8];
        const int dS = warp_window(sxh, (z - 1) * AXW + x0, AXROWS * AXW, tx, wS);
        extract4(wS, dS, sxw);                   // sxh[z-1][x .. x+3]
    }
    if (z <= NZ - 2) {   // warp-uniform
        float wS[8];
        const int dS = warp_window(szh, z * AZW + x0 - 1, AZROWS * AZW, tx, wS);
        extract4(wS, dS, szw);                   // szh[z][x-1 .. x+2]
    }

    // ---- Phase 1 (identical to the 136us kernel) ----
    float pReg[4] = {0.f, 0.f, 0.f, 0.f};
    const int g2 = z * NX + x;
    const int g3 = sOffP + g2;
    if (xact) {
        const float4 pxv = __ldcs((const float4*)(Px + g3));
        const float4 pzv = __ldcs((const float4*)(Pz + g3));
        const float4 srv = __ldcs((const float4*)(src + g3));
        const float4 mv  = *(const float4*)(m2dt + g2);
        const float4 sxv = *(const float4*)(sigx + g2);
        const float4 szv = *(const float4*)(sigz + g2);

        float axx[4] = {0.f, 0.f, 0.f, 0.f};
        float azz[4] = {0.f, 0.f, 0.f, 0.f};

        if (zin) {
            const float* axr  = Ax + sOffAx + (z - 1) * AXW;
            const float* az0r = Az + sOffAz + (z - 1) * AZW;
            const float* az1r = az0r + AZW;
            if (x >= 1 && x + 3 <= NX - 2) {
                const float a0 = __ldcs(axr + x - 1);
                axk[1] = __ldcs(axr + x);
                axk[2] = __ldcs(axr + x + 1);
                axk[3] = __ldcs(axr + x + 2);
                axk[4] = __ldcs(axr + x + 3);
                axx[0] = (axk[1] - a0)     * INV_H_F;
                axx[1] = (axk[2] - axk[1]) * INV_H_F;
                axx[2] = (axk[3] - axk[2]) * INV_H_F;
                axx[3] = (axk[4] - axk[3]) * INV_H_F;
                float azlo[4];
                #pragma unroll
                for (int c = 0; c < 4; c++) {
                    azlo[c] = __ldcs(az0r + x - 1 + c);
                    azk[c]  = __ldcs(az1r + x - 1 + c);
                    azz[c]  = (azk[c] - azlo[c]) * INV_H_F;
                }
            } else {
                float azlo[4] = {0.f, 0.f, 0.f, 0.f};
                #pragma unroll
                for (int c = 0; c < 5; c++) {
                    const int col = x - 1 + c;
                    if (col >= 0 && col <= NX - 2) axk[c] = __ldcs(axr + col);
                }
                #pragma unroll
                for (int c = 0; c < 4; c++) {
                    const int col = x - 1 + c;
                    if (col >= 0 && col <= NX - 3) {
                        azlo[c] = __ldcs(az0r + col);
                        azk[c]  = __ldcs(az1r + col);
                    }
                }
                #pragma unroll
                for (int c = 0; c < 4; c++) {
                    const int xi = x + c;
                    if (xi >= 1 && xi <= NX - 2) {
                        axx[c] = (axk[c + 1] - axk[c]) * INV_H_F;
                        azz[c] = (azk[c] - azlo[c]) * INV_H_F;
                    }
                }
            }
        }

        const float px_in[4] = {pxv.x, pxv.y, pxv.z, pxv.w};
        const float pz_in[4] = {pzv.x, pzv.y, pzv.z, pzv.w};
        const float sr_in[4] = {srv.x, srv.y, srv.z, srv.w};
        const float m_in[4]  = {mv.x, mv.y, mv.z, mv.w};
        const float sx_in[4] = {sxv.x, sxv.y, sxv.z, sxv.w};
        const float sz_in[4] = {szv.x, szv.y, szv.z, szv.w};

        float pxn[4], pzn[4];
        #pragma unroll
        for (int c = 0; c < 4; c++) {
            const float sx = sx_in[c] * HDT_F;
            const float sz = sz_in[c] * HDT_F;
            pxn[c] = __fdividef(fmaf(m_in[c], axx[c], (1.f - sx) * px_in[c]), 1.f + sx);
            pzn[c] = __fdividef(fmaf(m_in[c], azz[c], (1.f - sz) * pz_in[c]), 1.f + sz);
            pReg[c] = pxn[c] + pzn[c] + sr_in[c] * DT_F;
        }

        __stcs((float4*)(oPx + g3), make_float4(pxn[0], pxn[1], pxn[2], pxn[3]));
        __stcs((float4*)(oPz + g3), make_float4(pzn[0], pzn[1], pzn[2], pzn[3]));
        __stcs((float4*)(oP  + g3), make_float4(pReg[0], pReg[1], pReg[2], pReg[3]));
        *(float4*)&sP[ty][4 * tx] = make_float4(pReg[0], pReg[1], pReg[2], pReg[3]);
    }

    // z==0 fixup: phase 2b needs Az row 0 (zin was false)
    if (z == 0 && xact) {
        const float* az1r = Az + sOffAz;
        #pragma unroll
        for (int c = 0; c < 4; c++) {
            const int col = x - 1 + c;
            if (col >= 0 && col <= NX - 3) azk[c] = __ldcs(az1r + col);
        }
    }

    // ---- Halo P: bottom row + x-halo column ----
    if (tid < TILEW) {
        const int hz = z0 + TZ;
        const int hx = x0 + tid;
        if (hz < NZ && hx < NX)
            sP[TZ][tid] = compute_p_point(Px, Pz, Ax, Az, src, m2dt, sigx, sigz,
                                          sOffP, sOffAx, sOffAz, hz, hx);
    } else if (tid < TILEW + TZ) {
        const int r  = tid - TILEW;
        const int hx = x0 + TILEW;
        if (hx < NX)
            sP[r][TILEW] = compute_p_point(Px, Pz, Ax, Az, src, m2dt, sigx, sigz,
                                           sOffP, sOffAx, sOffAz, z0 + r, hx);
    }

    __syncthreads();

    // ---- Phase 2a: Ax_n row i = z-1 (warp-uniform; OOB lanes masked by jmax) ----
    if (zin) {
        float pe = __shfl_down_sync(0xffffffffu, pReg[0], 1);   // P[z][x+4]
        if (tx == 31) pe = sP[ty][TILEW];

        float vals[4];
        #pragma unroll
        for (int c = 0; c < 4; c++) {
            const float pnext = (c < 3) ? pReg[c + 1] : pe;
            const float dfx = (pnext - pReg[c]) * INV_H_F;
            const float sv  = sxw[c] * HDT_F;
            vals[c] = __fdividef(fmaf(DT_F, dfx, (1.f - sv) * axk[c + 1]), 1.f + sv);
        }
        warp_store_row(oAx, sOffAx + (z - 1) * AXW + x0, x0, AXW - 1, vals, tx);
    }

    // ---- Phase 2b: Az_n row i = z (warp-uniform) ----
    if (z <= NZ - 2) {
        const float4 pb = *(const float4*)&sP[ty + 1][4 * tx];
        const float pbv[4] = {pb.x, pb.y, pb.z, pb.w};

        float vals[4];
        #pragma unroll
        for (int c = 0; c < 4; c++) {
            const float dfz = (pbv[c] - pReg[c]) * INV_H_F;
            const float sv  = szw[c] * HDT_F;
            vals[c] = __fdividef(fmaf(DT_F, dfz, (1.f - sv) * azk[c]), 1.f + sv);
        }
        warp_store_row(oAz, sOffAz + z * AZW + x0 - 1, x0 - 1, AZW - 1, vals, tx);
    }
}

extern "C" void kernel_launch(void* const* d_in, const int* in_sizes, int n_in,
                              void* d_out, int out_size)
{
    const float* Px   = (const float*)d_in[0];
    const float* Pz   = (const float*)d_in[1];
    const float* Ax   = (const float*)d_in[2];
    const float* Az   = (const float*)d_in[3];
    const float* src  = (const float*)d_in[4];
    const float* m2dt = (const float*)d_in[5];
    const float* sigx = (const float*)d_in[6];
    const float* sxh  = (const float*)d_in[7];
    const float* sigz = (const float*)d_in[8];
    const float* szh  = (const float*)d_in[9];

    float* out = (float*)d_out;
    const long long NP  = (long long)NS * NZ * NX;
    const long long NAX = (long long)NS * AXROWS * AXW;
    const long long NAZ = (long long)NS * AZROWS * AZW;

    float* oPx = out;
    float* oPz = oPx + NP;
    float* oAx = oPz + NP;
    float* oAz = oAx + NAX;
    float* oP  = oAz + NAZ;

    dim3 block(32, TZ, 1);
    dim3 grid((NX + TILEW - 1) / TILEW, NZ / TZ, NS);

    pml_step_kernel<<<grid, block>>>(Px, Pz, Ax, Az, src,
                                     m2dt, sigx, sxh, sigz, szh,
                                     oPx, oPz, oAx, oAz, oP);
}